// round 17
// baseline (speedup 1.0000x reference)
#include <cuda_runtime.h>
#include <math.h>

#define NTOK 4096
#define EDIM 1024
#define NH   16
#define HD   32
#define NL   6

typedef unsigned long long u64;

// ---------------- scratch (device globals; no allocs allowed) ----------------
__device__ float g_z  [NTOK * EDIM];
__device__ float g_tmp[NTOK * EDIM];
__device__ float g_an [NTOK * EDIM];
__device__ float g_qkv[NTOK * 1536];        // [n][1536]: q | k | v
__device__ float g_o  [NTOK * NH * HD];     // [n][h*32+v]
__device__ float g_ff [NTOK * 2 * EDIM];
__device__ float g_wt [NL * EDIM * 1536];   // transposed QKV weights [l][e][c]

// ---------------- packed f32x2 helpers ----------------
__device__ __forceinline__ u64 ffma2(u64 a, u64 b, u64 c) {
    u64 r;
    asm("fma.rn.f32x2 %0, %1, %2, %3;" : "=l"(r) : "l"(a), "l"(b), "l"(c));
    return r;
}
__device__ __forceinline__ u64 fmul2(u64 a, u64 b) {
    u64 r;
    asm("mul.rn.f32x2 %0, %1, %2;" : "=l"(r) : "l"(a), "l"(b));
    return r;
}
__device__ __forceinline__ u64 packff(float x, float y) {
    u64 r;
    asm("mov.b64 %0, {%1, %2};" : "=l"(r) : "f"(x), "f"(y));
    return r;
}
__device__ __forceinline__ float2 unpackff(u64 v) {
    float2 f;
    asm("mov.b64 {%0, %1}, %2;" : "=f"(f.x), "=f"(f.y) : "l"(v));
    return f;
}
__device__ __forceinline__ void cpasync16(void* dst, const void* src) {
    unsigned d = (unsigned)__cvta_generic_to_shared(dst);
    asm volatile("cp.async.cg.shared.global [%0],[%1],16;" :: "r"(d), "l"(src) : "memory");
}
__device__ __forceinline__ void cpasync4(void* dst, const void* src) {
    unsigned d = (unsigned)__cvta_generic_to_shared(dst);
    asm volatile("cp.async.ca.shared.global [%0],[%1],4;" :: "r"(d), "l"(src) : "memory");
}
#define CP_COMMIT() asm volatile("cp.async.commit_group;" ::: "memory")
#define CP_WAIT0()  asm volatile("cp.async.wait_group 0;" ::: "memory")
#define CP_WAIT1()  asm volatile("cp.async.wait_group 1;" ::: "memory")

// ---------------- embedding: z = table[ctx] + pos ----------------
__global__ void embed_kernel(const int* __restrict__ ctx,
                             const float* __restrict__ table,
                             const float* __restrict__ pos) {
    int n = blockIdx.x, i = threadIdx.x;
    int tok = ctx[n];
    float4 a = ((const float4*)(table + (size_t)tok * EDIM))[i];
    float4 b = ((const float4*)(pos + (size_t)n * EDIM))[i];
    ((float4*)(g_z + (size_t)n * EDIM))[i] =
        make_float4(a.x + b.x, a.y + b.y, a.z + b.z, a.w + b.w);
}

// ---------------- weight transpose: g_wt[l][e][c], c = sel*512 + h*32 + v ----------------
__global__ void wt_kernel(const float* __restrict__ Wq,
                          const float* __restrict__ Wk,
                          const float* __restrict__ Wv) {
    int e = blockIdx.x;
    int l = blockIdx.y;
    #pragma unroll
    for (int i = 0; i < 6; i++) {
        int c = threadIdx.x + i * 256;
        int sel = c >> 9;
        int hv  = c & 511;
        const float* W = (sel == 0) ? Wq : (sel == 1) ? Wk : Wv;
        g_wt[((size_t)l * EDIM + e) * 1536 + c] =
            W[(size_t)l * 524288 + (size_t)(hv >> 5) * 32768 + (size_t)e * 32 + (hv & 31)];
    }
}

// ---------------- f32x2 SIMT GEMM: C[M,N] = A[M,K] @ B[K,N] ----------------
// 128x64 block tile, BK=16, 128 threads, 8x8 microtile (acc pairs along N).
// A staged TRANSPOSED As[k][128] via 4B cp.async -> conflict-free a reads.
// EPI: 0 none (qkv); 1 bias+leaky (ff1); 2 bias+res (ff2); 3 res (oproj)
template<int EPI>
__global__ __launch_bounds__(128)
void f2gemm_kernel(const float* __restrict__ A, const float* __restrict__ B,
                   const float* __restrict__ bias, const float* __restrict__ res,
                   float* __restrict__ C, int N, int K) {
    __shared__ __align__(16) float As[2][16 * 128];   // [k][m] transposed
    __shared__ __align__(16) float Bs[2][16 * 64];    // [k][n]
    const int t = threadIdx.x;
    const int tx = t & 7;            // 8 col-groups of 8
    const int ty8 = (t >> 3) * 8;    // 16 row-groups of 8
    const int by = blockIdx.y * 128, bx = blockIdx.x * 64;

    u64 acc[8][4];
    #pragma unroll
    for (int i = 0; i < 8; i++)
        #pragma unroll
        for (int j = 0; j < 4; j++) acc[i][j] = 0ull;

    const int KT = K >> 4;
    const int arow = t >> 4;   // 0..7 (base row within 8-row pass)
    const int acol = t & 15;   // k index

    auto stage = [&](int kt) {
        int buf = kt & 1, k0 = kt * 16;
        // A: 128 rows x 16 k, transposed into As[k][m]; 16 passes x 8 rows
        #pragma unroll
        for (int p = 0; p < 16; p++) {
            int row = p * 8 + arow;
            cpasync4(&As[buf][acol * 128 + row],
                     A + (size_t)(by + row) * K + k0 + acol);
        }
        // B: 16 rows x 64 cols, row-major, 16B chunks
        #pragma unroll
        for (int i = 0; i < 2; i++) {
            int gi = i * 128 + t;
            int r = gi >> 4, c = gi & 15;
            cpasync16(&Bs[buf][r * 64 + c * 4], B + (size_t)(k0 + r) * N + bx + c * 4);
        }
        CP_COMMIT();
    };

    auto compute = [&](int kt) {
        int buf = kt & 1;
        const float* Ak = &As[buf][ty8];
        const float* Bb = &Bs[buf][tx * 8];
        #pragma unroll
        for (int k = 0; k < 16; k++) {
            float4 a0 = *(const float4*)&Ak[k * 128];
            float4 a1 = *(const float4*)&Ak[k * 128 + 4];
            u64 bd[4];
            const u64* bp = (const u64*)(Bb + k * 64);
            #pragma unroll
            for (int j = 0; j < 4; j++) bd[j] = bp[j];
            u64 ad[8];
            ad[0] = packff(a0.x, a0.x); ad[1] = packff(a0.y, a0.y);
            ad[2] = packff(a0.z, a0.z); ad[3] = packff(a0.w, a0.w);
            ad[4] = packff(a1.x, a1.x); ad[5] = packff(a1.y, a1.y);
            ad[6] = packff(a1.z, a1.z); ad[7] = packff(a1.w, a1.w);
            #pragma unroll
            for (int i = 0; i < 8; i++)
                #pragma unroll
                for (int j = 0; j < 4; j++)
                    acc[i][j] = ffma2(ad[i], bd[j], acc[i][j]);
        }
    };

    stage(0);
    for (int kt = 0; kt < KT; kt++) {
        if (kt + 1 < KT) { stage(kt + 1); CP_WAIT1(); }
        else { CP_WAIT0(); }
        __syncthreads();
        compute(kt);
        __syncthreads();
    }

    // epilogue
    #pragma unroll
    for (int i = 0; i < 8; i++) {
        int row = by + ty8 + i;
        #pragma unroll
        for (int j = 0; j < 4; j++) {
            int col = bx + tx * 8 + j * 2;
            float2 v = unpackff(acc[i][j]);
            if (EPI == 1 || EPI == 2) {
                float2 bv = *(const float2*)&bias[col];
                v.x += bv.x; v.y += bv.y;
            }
            if (EPI == 1) {
                v.x = (v.x > 0.f) ? v.x : 0.01f * v.x;
                v.y = (v.y > 0.f) ? v.y : 0.01f * v.y;
            }
            if (EPI == 2 || EPI == 3) {
                float2 rv = *(const float2*)&res[(size_t)row * N + col];
                v.x += rv.x; v.y += rv.y;
            }
            *(float2*)&C[(size_t)row * N + col] = v;
        }
    }
}

// ---------------- flash attention (SIMT f32x2, cp.async double-buffered) ----------------
// grid (NTOK/128, NH), block 128. One query row per thread. Reads g_qkv [n][1536].
__global__ __launch_bounds__(128)
void attn_kernel() {
    __shared__ __align__(16) float Ks[2][32][32];
    __shared__ __align__(16) float Vs[2][32][32];
    int h = blockIdx.y;
    int qrow = blockIdx.x * 128 + threadIdx.x;
    const float scale = 0.17677669529663687f;   // 1/sqrt(32)
    int t = threadIdx.x;

    u64 q2[16], o2[16];
    const float* qp = g_qkv + (size_t)qrow * 1536 + h * 32;
    #pragma unroll
    for (int v4 = 0; v4 < 8; v4++) {
        float4 t4 = *(const float4*)&qp[v4 * 4];
        q2[v4 * 2 + 0] = packff(t4.x * scale, t4.y * scale);
        q2[v4 * 2 + 1] = packff(t4.z * scale, t4.w * scale);
    }
    #pragma unroll
    for (int d = 0; d < 16; d++) o2[d] = 0ull;
    float m = -1e30f, l = 0.f;

    const float* kbase = g_qkv + 512 + h * 32;
    const float* vbase = g_qkv + 1024 + h * 32;

    auto issue = [&](int kt) {
        int buf = kt & 1;
        #pragma unroll
        for (int i = 0; i < 4; i++) {
            int gi = i * 128 + t;            // 0..511
            int isV = gi >> 8;               // 0: K, 1: V
            int wdx = gi & 255;
            int r = wdx >> 3, c4 = wdx & 7;
            const float* src = (isV ? vbase : kbase)
                             + (size_t)(kt * 32 + r) * 1536 + c4 * 4;
            float* dst = (isV ? &Vs[buf][r][c4 * 4] : &Ks[buf][r][c4 * 4]);
            cpasync16(dst, src);
        }
        CP_COMMIT();
    };

    issue(0);
    const int NT = NTOK / 32;
    for (int kt = 0; kt < NT; kt++) {
        if (kt + 1 < NT) { issue(kt + 1); CP_WAIT1(); }
        else { CP_WAIT0(); }
        __syncthreads();
        int buf = kt & 1;

        float s[32];
        float mloc = -1e30f;
        #pragma unroll
        for (int j = 0; j < 32; j++) {
            u64 a0 = 0ull, a1 = 0ull;
            const ulonglong2* kk = (const ulonglong2*)Ks[buf][j];
            #pragma unroll
            for (int v = 0; v < 8; v++) {
                ulonglong2 p2 = kk[v];
                a0 = ffma2(q2[2 * v], p2.x, a0);
                a1 = ffma2(q2[2 * v + 1], p2.y, a1);
            }
            float2 f0 = unpackff(a0), f1 = unpackff(a1);
            float acc = (f0.x + f0.y) + (f1.x + f1.y);
            s[j] = acc;
            mloc = fmaxf(mloc, acc);
        }
        float mnew = fmaxf(m, mloc);
        float alpha = __expf(m - mnew);
        float psum = 0.f;
        #pragma unroll
        for (int j = 0; j < 32; j++) {
            s[j] = __expf(s[j] - mnew);
            psum += s[j];
        }
        l = l * alpha + psum;
        u64 ad = packff(alpha, alpha);
        #pragma unroll
        for (int d = 0; d < 16; d++) o2[d] = fmul2(o2[d], ad);
        #pragma unroll
        for (int j = 0; j < 32; j++) {
            u64 pd = packff(s[j], s[j]);
            const ulonglong2* vv = (const ulonglong2*)Vs[buf][j];
            #pragma unroll
            for (int v = 0; v < 8; v++) {
                ulonglong2 v2 = vv[v];
                o2[2 * v]     = ffma2(pd, v2.x, o2[2 * v]);
                o2[2 * v + 1] = ffma2(pd, v2.y, o2[2 * v + 1]);
            }
        }
        m = mnew;
        __syncthreads();
    }

    float inv = 1.f / l;
    float* op = g_o + (size_t)qrow * (NH * HD) + (size_t)h * HD;
    #pragma unroll
    for (int d = 0; d < 8; d++) {
        float2 a = unpackff(o2[2 * d]);
        float2 b = unpackff(o2[2 * d + 1]);
        *(float4*)&op[d * 4] = make_float4(a.x * inv, a.y * inv, b.x * inv, b.y * inv);
    }
}

// ---------------- row LayerNorm (ddof=1, no eps), E=1024, 256 threads ----------------
__global__ __launch_bounds__(256)
void ln_kernel(const float* __restrict__ in, float* __restrict__ out) {
    int n = blockIdx.x;
    const float* x = in + (size_t)n * EDIM;
    float xv[4], s1 = 0.f, s2 = 0.f;
    #pragma unroll
    for (int i = 0; i < 4; i++) {
        float v = x[threadIdx.x + i * 256];
        xv[i] = v; s1 += v; s2 += v * v;
    }
    #pragma unroll
    for (int off = 16; off; off >>= 1) {
        s1 += __shfl_down_sync(0xffffffffu, s1, off);
        s2 += __shfl_down_sync(0xffffffffu, s2, off);
    }
    __shared__ float r1[8], r2[8];
    __shared__ float mean_s, inv_s;
    int w = threadIdx.x >> 5;
    if ((threadIdx.x & 31) == 0) { r1[w] = s1; r2[w] = s2; }
    __syncthreads();
    if (threadIdx.x == 0) {
        float a = 0.f, b = 0.f;
        #pragma unroll
        for (int i = 0; i < 8; i++) { a += r1[i]; b += r2[i]; }
        float mean = a / (float)EDIM;
        mean_s = mean;
        inv_s = rsqrtf((b - (float)EDIM * mean * mean) / (float)(EDIM - 1));
    }
    __syncthreads();
    float mean = mean_s, inv = inv_s;
    #pragma unroll
    for (int i = 0; i < 4; i++)
        out[(size_t)n * EDIM + threadIdx.x + i * 256] = (xv[i] - mean) * inv;
}

// ---------------- host orchestration ----------------
extern "C" void kernel_launch(void* const* d_in, const int* in_sizes, int n_in,
                              void* d_out, int out_size) {
    const int*   ctx   = (const int*)  d_in[0];
    const float* table = (const float*)d_in[1];
    const float* pos   = (const float*)d_in[2];
    const float* Wq    = (const float*)d_in[3];
    const float* Wk    = (const float*)d_in[4];
    const float* Wv    = (const float*)d_in[5];
    const float* Wo    = (const float*)d_in[6];
    const float* W1    = (const float*)d_in[7];
    const float* b1    = (const float*)d_in[8];
    const float* W2    = (const float*)d_in[9];
    const float* b2    = (const float*)d_in[10];

    float *z, *tmp, *an, *qkv, *o, *ff, *wt;
    cudaGetSymbolAddress((void**)&z,   g_z);
    cudaGetSymbolAddress((void**)&tmp, g_tmp);
    cudaGetSymbolAddress((void**)&an,  g_an);
    cudaGetSymbolAddress((void**)&qkv, g_qkv);
    cudaGetSymbolAddress((void**)&o,   g_o);
    cudaGetSymbolAddress((void**)&ff,  g_ff);
    cudaGetSymbolAddress((void**)&wt,  g_wt);

    embed_kernel<<<NTOK, 256>>>(ctx, table, pos);
    wt_kernel<<<dim3(EDIM, NL), 256>>>(Wq, Wk, Wv);

    const size_t wo_stride = (size_t)NH * HD * EDIM;
    const size_t w1_stride = (size_t)EDIM * 2 * EDIM;
    const size_t w2_stride = (size_t)2 * EDIM * EDIM;

    for (int l = 0; l < NL; l++) {
        const float* wtl = wt + (size_t)l * EDIM * 1536;
        const float* wo  = Wo + (size_t)l * wo_stride;
        const float* w1  = W1 + (size_t)l * w1_stride;
        const float* bb1 = b1 + (size_t)l * 2 * EDIM;
        const float* w2  = W2 + (size_t)l * w2_stride;
        const float* bb2 = b2 + (size_t)l * EDIM;

        // qkv = z @ Wt   [4096 x 1536], K=1024
        f2gemm_kernel<0><<<dim3(1536 / 64, NTOK / 128), 128>>>(
            z, wtl, nullptr, nullptr, qkv, 1536, EDIM);

        attn_kernel<<<dim3(NTOK / 128, NH), 128>>>();

        // tmp = z + o @ Wo   [4096 x 1024], K=512
        f2gemm_kernel<3><<<dim3(EDIM / 64, NTOK / 128), 128>>>(
            o, wo, nullptr, z, tmp, EDIM, NH * HD);
        ln_kernel<<<NTOK, 256>>>(tmp, an);

        // ff = leaky(an @ W1 + b1)   [4096 x 2048], K=1024
        f2gemm_kernel<1><<<dim3(2 * EDIM / 64, NTOK / 128), 128>>>(
            an, w1, bb1, nullptr, ff, 2 * EDIM, EDIM);

        // tmp = an + ff @ W2 + b2   [4096 x 1024], K=2048
        f2gemm_kernel<2><<<dim3(EDIM / 64, NTOK / 128), 128>>>(
            ff, w2, bb2, an, tmp, EDIM, 2 * EDIM);

        ln_kernel<<<NTOK, 256>>>(tmp, (l == NL - 1) ? (float*)d_out : z);
    }
}